// round 12
// baseline (speedup 1.0000x reference)
#include <cuda_runtime.h>
#include <cuda_fp16.h>
#include <cstdint>

#define BATCH 8
#define CH 64
#define NPTS 65536
#define RR 32
#define NVOX 32768  // 32^3

// ---------------- scratch (__device__ globals; no allocation allowed) ------
__device__ float d_mean[BATCH * 3];
__device__ float d_scale[BATCH];
__device__ float d_voxc[BATCH * 3 * NPTS];            // clipped voxel coords
__device__ float d_cnt[BATCH * NVOX];                 // per-voxel point counts
__device__ float d_grid0[(size_t)BATCH * NVOX * CH];  // scatter SUMS (not averaged)
__device__ float d_grid1[(size_t)BATCH * NVOX * CH];  // after conv1
__device__ float d_grid2[(size_t)BATCH * NVOX * CH];  // after conv2
__device__ __half d_wH1[27 * 64 * 64];                // [tap][oc][ic] fp16, BN folded
__device__ __half d_wH2[27 * 64 * 64];
__device__ float d_biasE1[64];
__device__ float d_biasE2[64];

// ---------------- helpers ---------------------------------------------------
__device__ __forceinline__ unsigned h2_as_u32(__half2 h) {
    return *reinterpret_cast<unsigned*>(&h);
}
__device__ __forceinline__ void mma_f16(float& d0, float& d1, float& d2, float& d3,
                                        unsigned a0, unsigned a1, unsigned a2, unsigned a3,
                                        unsigned b0, unsigned b1) {
    asm("mma.sync.aligned.m16n8k16.row.col.f32.f16.f16.f32 "
        "{%0,%1,%2,%3},{%4,%5,%6,%7},{%8,%9},{%0,%1,%2,%3};"
        : "+f"(d0), "+f"(d1), "+f"(d2), "+f"(d3)
        : "r"(a0), "r"(a1), "r"(a2), "r"(a3), "r"(b0), "r"(b1));
}
__device__ __forceinline__ void ldsm_x4(unsigned& r0, unsigned& r1, unsigned& r2,
                                        unsigned& r3, uint32_t addr) {
    asm volatile("ldmatrix.sync.aligned.m8n8.x4.shared.b16 {%0,%1,%2,%3}, [%4];"
                 : "=r"(r0), "=r"(r1), "=r"(r2), "=r"(r3) : "r"(addr));
}

// ============ launch #1: fused zero + mean/scale + weight prep ==============
#define ZBLK 16640
#define PBLK 432
__global__ void fused_init_kernel(const float* __restrict__ coords,
                                  const float* __restrict__ w1, const float* __restrict__ b1,
                                  const float* __restrict__ g1, const float* __restrict__ be1,
                                  const float* __restrict__ m1, const float* __restrict__ v1,
                                  const float* __restrict__ w2, const float* __restrict__ b2,
                                  const float* __restrict__ g2, const float* __restrict__ be2,
                                  const float* __restrict__ m2, const float* __restrict__ v2) {
    __shared__ float red[3][256];
    int blk = blockIdx.x;
    int tid = threadIdx.x;

    if (blk < ZBLK) {
        size_t t = (size_t)blk * 256 + tid;
        const size_t g4 = (size_t)BATCH * NVOX * CH / 4;
        float4 z = make_float4(0.f, 0.f, 0.f, 0.f);
        if (t < g4) {
            reinterpret_cast<float4*>(d_grid0)[t] = z;
        } else {
            size_t u = t - g4;
            if (u < (size_t)BATCH * NVOX / 4) reinterpret_cast<float4*>(d_cnt)[u] = z;
        }
        return;
    }
    if (blk < ZBLK + BATCH) {
        int b = blk - ZBLK;
        const float* cb = coords + (size_t)b * 3 * NPTS;
        float s0 = 0.f, s1 = 0.f, s2 = 0.f;
        for (int n = tid; n < NPTS; n += 256) {
            s0 += cb[n];
            s1 += cb[NPTS + n];
            s2 += cb[2 * NPTS + n];
        }
        red[0][tid] = s0; red[1][tid] = s1; red[2][tid] = s2;
        __syncthreads();
        for (int off = 128; off > 0; off >>= 1) {
            if (tid < off) {
                red[0][tid] += red[0][tid + off];
                red[1][tid] += red[1][tid + off];
                red[2][tid] += red[2][tid + off];
            }
            __syncthreads();
        }
        float m0 = red[0][0] / (float)NPTS;
        float m1 = red[1][0] / (float)NPTS;
        float m2 = red[2][0] / (float)NPTS;
        __syncthreads();
        float mx = 0.f;
        for (int n = tid; n < NPTS; n += 256) {
            float dx = cb[n] - m0;
            float dy = cb[NPTS + n] - m1;
            float dz = cb[2 * NPTS + n] - m2;
            mx = fmaxf(mx, dx * dx + dy * dy + dz * dz);
        }
        red[0][tid] = mx;
        __syncthreads();
        for (int off = 128; off > 0; off >>= 1) {
            if (tid < off) red[0][tid] = fmaxf(red[0][tid], red[0][tid + off]);
            __syncthreads();
        }
        if (tid == 0) {
            d_mean[b * 3 + 0] = m0;
            d_mean[b * 3 + 1] = m1;
            d_mean[b * 3 + 2] = m2;
            d_scale[b] = sqrtf(red[0][0]);
        }
        return;
    }
    // weight prep: fp16 [tap][oc][ic] with BN scale folded, + bias
    const float *w, *bs, *g, *be, *m, *v;
    __half* wH; float* biasE;
    int i;
    if (blk < ZBLK + BATCH + PBLK) {
        i = (blk - ZBLK - BATCH) * 256 + tid;
        w = w1; bs = b1; g = g1; be = be1; m = m1; v = v1; wH = d_wH1; biasE = d_biasE1;
    } else {
        i = (blk - ZBLK - BATCH - PBLK) * 256 + tid;
        w = w2; bs = b2; g = g2; be = be2; m = m2; v = v2; wH = d_wH2; biasE = d_biasE2;
    }
    if (i < 64) {
        float sc = g[i] * rsqrtf(v[i] + 1e-4f);
        biasE[i] = (bs[i] - m[i]) * sc + be[i];
    }
    if (i < 27 * 64 * 64) {
        int ic = i & 63;
        int oc = (i >> 6) & 63;
        int tap = i >> 12;
        float sc = g[oc] * rsqrtf(v[oc] + 1e-4f);
        wH[i] = __float2half_rn(w[(oc * 64 + ic) * 27 + tap] * sc);
    }
}

// ============ launch #2: transpose-scatter (+ inline voxelize) ==============
// grid (NPTS/32, 2 c-halves, BATCH), block (32, 8).
__global__ void trans_scatter_kernel(const float* __restrict__ f,
                                     const float* __restrict__ coords) {
    __shared__ float tile[32][33];     // [c][n]
    int b = blockIdx.z;
    int c0 = blockIdx.y * 32;
    int n0 = blockIdx.x * 32;
    int tx = threadIdx.x, ty = threadIdx.y;
    const float* fb = f + (size_t)b * CH * NPTS;
#pragma unroll
    for (int i = 0; i < 4; i++) {
        int c = c0 + ty + i * 8;
        tile[ty + i * 8][tx] = fb[(size_t)c * NPTS + n0 + tx];
    }
    __syncthreads();
    int n = n0 + tx;
    // inline voxelize (recomputed per c-half; cheap)
    const float* cb = coords + (size_t)b * 3 * NPTS;
    float m0 = d_mean[b * 3 + 0], m1 = d_mean[b * 3 + 1], m2 = d_mean[b * 3 + 2];
    float den = d_scale[b] * 2.0f;
    float vx = fminf(fmaxf(((cb[n]            - m0) / den + 0.5f) * 32.0f, 0.f), 31.f);
    float vy = fminf(fmaxf(((cb[NPTS + n]     - m1) / den + 0.5f) * 32.0f, 0.f), 31.f);
    float vz = fminf(fmaxf(((cb[2 * NPTS + n] - m2) / den + 0.5f) * 32.0f, 0.f), 31.f);
    int idx = (((int)rintf(vx)) * 32 + (int)rintf(vy)) * 32 + (int)rintf(vz);
    if (blockIdx.y == 0 && ty == 0) {
        float* vout = d_voxc + (size_t)b * 3 * NPTS;
        vout[n] = vx;
        vout[NPTS + n] = vy;
        vout[2 * NPTS + n] = vz;
        atomicAdd(&d_cnt[b * NVOX + idx], 1.0f);
    }
    float* gb = &d_grid0[((size_t)b * NVOX + idx) * CH + c0 + ty * 4];
    float v0 = tile[ty * 4 + 0][tx];
    float v1 = tile[ty * 4 + 1][tx];
    float v2 = tile[ty * 4 + 2][tx];
    float v3 = tile[ty * 4 + 3][tx];
    asm volatile("red.global.add.v4.f32 [%0], {%1, %2, %3, %4};"
                 :: "l"(gb), "f"(v0), "f"(v1), "f"(v2), "f"(v3) : "memory");
}

// ============ launches #3/#4: conv — fp16 HMMA m64n32/warp, swizzled ========
// Tile 4x8x8 = 256 vox, 256 threads (8 warps), warp = m64 x n32, K=64/tap.
// Warp w: voxel-group g=w>>1 (x = x0+g, y[0,8), z[0,8) = m64), oc-half w&1.
// Halo 6x10x10 rows x 128B fp16, XOR-swizzled (chunk c of row r at c^(r&7)):
// ldmatrix conflict-free without padding. Weights [oc][ic] fp16 swizzled,
// 2-stage cp.async ring, 1 barrier/tap. conv1 fuses 1/cnt averaging.
#define C_HROWS 600
#define C_INH (C_HROWS * 64)              // 38400 halfs
#define C_WSTAGE (64 * 64)                // 4096 halfs per stage
#define C_SMEM ((C_INH + 2 * C_WSTAGE) * 2)  // 93184 bytes

__device__ __forceinline__ void stage_weights(const __half* __restrict__ wH, int tap,
                                              uint32_t dst_base, int tid) {
#pragma unroll
    for (int i = 0; i < 2; i++) {
        int idx = tid + i * 256;          // [0,512) 16B chunks
        int row = idx >> 3, c = idx & 7;
        uint32_t d = dst_base + (uint32_t)(row * 128 + ((c ^ (row & 7)) << 4));
        asm volatile("cp.async.cg.shared.global [%0], [%1], 16;"
                     :: "r"(d), "l"(wH + tap * 4096 + row * 64 + c * 8) : "memory");
    }
}

__global__ void __launch_bounds__(256, 2) conv_tc_kernel(const float* __restrict__ gin,
                                                         float* __restrict__ gout,
                                                         const __half* __restrict__ wH,
                                                         const float* __restrict__ biasE,
                                                         const float* __restrict__ cnt) {
    extern __shared__ __half shh[];
    __half* in_sh = shh;
    uint32_t insh_u32 = (uint32_t)__cvta_generic_to_shared(in_sh);
    uint32_t wsh_u32 = insh_u32 + C_INH * 2;   // 2 weight stages follow halo

    int tid = threadIdx.x;
    int bx = blockIdx.x;
    int b = bx >> 7;                       // 128 tiles/batch
    int tile = bx & 127;
    int x0 = (tile >> 4) * 4;
    int y0 = ((tile >> 2) & 3) * 8;
    int z0 = (tile & 3) * 8;

    stage_weights(wH, 0, wsh_u32, tid);
    asm volatile("cp.async.commit_group;" ::: "memory");

    // halo: 600 rows x 128B fp16, zero-pad, XOR-swizzled; conv1 scales by 1/cnt
    for (int s = tid; s < C_HROWS * 8; s += 256) {
        int vox = s >> 3, c8 = s & 7;
        int hx = vox / 100;
        int r = vox - hx * 100;
        int hy = r / 10;
        int hz = r - hy * 10;
        int gx = x0 + hx - 1, gy = y0 + hy - 1, gz = z0 + hz - 1;
        float4 lo = make_float4(0.f, 0.f, 0.f, 0.f);
        float4 hi = make_float4(0.f, 0.f, 0.f, 0.f);
        if ((unsigned)gx < 32u && (unsigned)gy < 32u && (unsigned)gz < 32u) {
            size_t gvox = (((size_t)b * 32 + gx) * 32 + gy) * 32 + gz;
            const float4* src = reinterpret_cast<const float4*>(&gin[gvox * CH + c8 * 8]);
            lo = src[0];
            hi = src[1];
            if (cnt) {
                float inv = 1.0f / fmaxf(cnt[gvox], 1.0f);
                lo.x *= inv; lo.y *= inv; lo.z *= inv; lo.w *= inv;
                hi.x *= inv; hi.y *= inv; hi.z *= inv; hi.w *= inv;
            }
        }
        uint4 pk;
        pk.x = h2_as_u32(__floats2half2_rn(lo.x, lo.y));
        pk.y = h2_as_u32(__floats2half2_rn(lo.z, lo.w));
        pk.z = h2_as_u32(__floats2half2_rn(hi.x, hi.y));
        pk.w = h2_as_u32(__floats2half2_rn(hi.z, hi.w));
        *reinterpret_cast<uint4*>(in_sh + vox * 64 + ((c8 ^ (vox & 7)) << 3)) = pk;
    }

    int w = tid >> 5;                      // warp [0,8)
    int lane = tid & 31;
    int g = w >> 1;                        // voxel group: x = x0 + g
    int och = w & 1;                       // oc half (n32)
    int yq = (lane >> 3) & 1;              // m8 selector within m16
    int lr = lane & 7;                     // z row
    int kh = lane >> 4;                    // k8 half selector

    // A base rows per m16 tile i: voxel (x=g, y=2i+yq, z=lr)
    int aRow0[4];
#pragma unroll
    for (int i = 0; i < 4; i++) aRow0[i] = g * 100 + (2 * i + yq) * 10 + lr;
    // B lane offsets (fixed across taps, relative to stage base)
    int ocL = och * 32 + yq * 8 + lr;
    uint32_t Brow0 = (uint32_t)(ocL * 128);
    uint32_t Brow1 = Brow0 + 16 * 128;
    int swB = (lr & 7) << 4;

    float acc[4][4][4];
#pragma unroll
    for (int i = 0; i < 4; i++)
#pragma unroll
        for (int nb = 0; nb < 4; nb++)
#pragma unroll
            for (int j = 0; j < 4; j++) acc[i][nb][j] = 0.f;

    int slot = 0;
    for (int tap = 0; tap < 27; tap++) {
        asm volatile("cp.async.wait_group 0;" ::: "memory");
        __syncthreads();
        if (tap + 1 < 27) {
            stage_weights(wH, tap + 1, wsh_u32 + (uint32_t)(slot ^ 1) * (C_WSTAGE * 2), tid);
            asm volatile("cp.async.commit_group;" ::: "memory");
        }

        int dxi = tap / 9;
        int rr9 = tap - dxi * 9;
        int dyi = rr9 / 3;
        int dzi = rr9 - dyi * 3;
        int dr = dxi * 100 + dyi * 10 + dzi;

        uint32_t aAddr[4];
        int asw[4];
#pragma unroll
        for (int i = 0; i < 4; i++) {
            int rr = aRow0[i] + dr;
            aAddr[i] = insh_u32 + ((uint32_t)rr << 7);
            asw[i] = (rr & 7) << 4;
        }
        uint32_t wb = wsh_u32 + (uint32_t)slot * (C_WSTAGE * 2);

#pragma unroll
        for (int kc = 0; kc < 4; kc++) {
            int ck = (kc * 2 + kh) << 4;
            unsigned A[4][4], Bl[4], Bh[4];
#pragma unroll
            for (int i = 0; i < 4; i++)
                ldsm_x4(A[i][0], A[i][1], A[i][2], A[i][3],
                        aAddr[i] + (uint32_t)(ck ^ asw[i]));
            ldsm_x4(Bl[0], Bl[1], Bl[2], Bl[3], wb + Brow0 + (uint32_t)(ck ^ swB));
            ldsm_x4(Bh[0], Bh[1], Bh[2], Bh[3], wb + Brow1 + (uint32_t)(ck ^ swB));
#pragma unroll
            for (int i = 0; i < 4; i++) {
                mma_f16(acc[i][0][0], acc[i][0][1], acc[i][0][2], acc[i][0][3],
                        A[i][0], A[i][1], A[i][2], A[i][3], Bl[0], Bl[2]);
                mma_f16(acc[i][1][0], acc[i][1][1], acc[i][1][2], acc[i][1][3],
                        A[i][0], A[i][1], A[i][2], A[i][3], Bl[1], Bl[3]);
                mma_f16(acc[i][2][0], acc[i][2][1], acc[i][2][2], acc[i][2][3],
                        A[i][0], A[i][1], A[i][2], A[i][3], Bh[0], Bh[2]);
                mma_f16(acc[i][3][0], acc[i][3][1], acc[i][3][2], acc[i][3][3],
                        A[i][0], A[i][1], A[i][2], A[i][3], Bh[1], Bh[3]);
            }
        }
        slot ^= 1;
    }

    // epilogue: tile i -> y = y0+2i (c0/c1) and y0+2i+1 (c2/c3); z = lane>>2
    int zq = lane >> 2;
    int kq = lane & 3;
    int X = x0 + g;
    int Z = z0 + zq;
#pragma unroll
    for (int i = 0; i < 4; i++) {
        size_t base_lo = ((((size_t)b * 32 + X) * 32 + (y0 + 2 * i)) * 32 + Z) * CH;
        size_t base_hi = base_lo + 32 * CH;
#pragma unroll
        for (int nb = 0; nb < 4; nb++) {
            int oc = och * 32 + nb * 8 + 2 * kq;
            float2 bb = *reinterpret_cast<const float2*>(&biasE[oc]);
            float y00 = acc[i][nb][0] + bb.x;
            float y01 = acc[i][nb][1] + bb.y;
            float y10 = acc[i][nb][2] + bb.x;
            float y11 = acc[i][nb][3] + bb.y;
            y00 = (y00 >= 0.f) ? y00 : 0.1f * y00;
            y01 = (y01 >= 0.f) ? y01 : 0.1f * y01;
            y10 = (y10 >= 0.f) ? y10 : 0.1f * y10;
            y11 = (y11 >= 0.f) ? y11 : 0.1f * y11;
            *reinterpret_cast<float2*>(&gout[base_lo + oc]) = make_float2(y00, y01);
            *reinterpret_cast<float2*>(&gout[base_hi + oc]) = make_float2(y10, y11);
        }
    }
}

// ============ launch #5: trilinear devoxelize (+ coords echo) ===============
__global__ void devox_kernel(float* __restrict__ out, const float* __restrict__ grid,
                             const float* __restrict__ coords) {
    int n = blockIdx.x * 256 + threadIdx.x;
    int cg = blockIdx.y;
    int b = blockIdx.z;
    if (cg == 16) {   // coords echo
        float* out2 = out + (size_t)BATCH * CH * NPTS;
        size_t base = (size_t)b * 3 * NPTS;
        out2[base + n] = coords[base + n];
        out2[base + NPTS + n] = coords[base + NPTS + n];
        out2[base + 2 * NPTS + n] = coords[base + 2 * NPTS + n];
        return;
    }
    const float* vc = d_voxc + (size_t)b * 3 * NPTS;
    float cx = vc[n], cy = vc[NPTS + n], cz = vc[2 * NPTS + n];
    int ix0 = (int)floorf(cx), iy0 = (int)floorf(cy), iz0 = (int)floorf(cz);
    float fx = cx - (float)ix0, fy = cy - (float)iy0, fz = cz - (float)iz0;
    int ix1 = min(ix0 + 1, 31), iy1 = min(iy0 + 1, 31), iz1 = min(iz0 + 1, 31);
    float gx0 = 1.f - fx, gy0 = 1.f - fy, gz0 = 1.f - fz;

    const float* g = grid + ((size_t)b * NVOX) * CH + cg * 4;
    float4 acc = make_float4(0.f, 0.f, 0.f, 0.f);

#define CORNER(XI, YI, ZI, W)                                                        \
    {                                                                                \
        float4 cv = *reinterpret_cast<const float4*>(                                \
            &g[(size_t)(((XI) * 32 + (YI)) * 32 + (ZI)) * CH]);                      \
        float ww = (W);                                                              \
        acc.x += ww * cv.x; acc.y += ww * cv.y; acc.z += ww * cv.z; acc.w += ww * cv.w; \
    }
    CORNER(ix0, iy0, iz0, gx0 * gy0 * gz0)
    CORNER(ix0, iy0, iz1, gx0 * gy0 * fz)
    CORNER(ix0, iy1, iz0, gx0 * fy * gz0)
    CORNER(ix0, iy1, iz1, gx0 * fy * fz)
    CORNER(ix1, iy0, iz0, fx * gy0 * gz0)
    CORNER(ix1, iy0, iz1, fx * gy0 * fz)
    CORNER(ix1, iy1, iz0, fx * fy * gz0)
    CORNER(ix1, iy1, iz1, fx * fy * fz)
#undef CORNER

    size_t ob = ((size_t)b * CH + cg * 4) * NPTS + n;
    out[ob] = acc.x;
    out[ob + NPTS] = acc.y;
    out[ob + 2 * (size_t)NPTS] = acc.z;
    out[ob + 3 * (size_t)NPTS] = acc.w;
}

// ---------------- launch ----------------------------------------------------
extern "C" void kernel_launch(void* const* d_in, const int* in_sizes, int n_in,
                              void* d_out, int out_size) {
    (void)in_sizes; (void)n_in; (void)out_size;
    const float* feats  = (const float*)d_in[0];
    const float* coords = (const float*)d_in[1];
    const float* w1  = (const float*)d_in[2];
    const float* b1  = (const float*)d_in[3];
    const float* g1  = (const float*)d_in[4];
    const float* be1 = (const float*)d_in[5];
    const float* m1  = (const float*)d_in[6];
    const float* v1  = (const float*)d_in[7];
    const float* w2  = (const float*)d_in[8];
    const float* b2  = (const float*)d_in[9];
    const float* g2  = (const float*)d_in[10];
    const float* be2 = (const float*)d_in[11];
    const float* m2  = (const float*)d_in[12];
    const float* v2  = (const float*)d_in[13];
    float* out = (float*)d_out;

    float *p_g0, *p_g1, *p_g2, *p_be1, *p_be2, *p_cnt;
    __half *p_wH1, *p_wH2;
    cudaGetSymbolAddress((void**)&p_g0, d_grid0);
    cudaGetSymbolAddress((void**)&p_g1, d_grid1);
    cudaGetSymbolAddress((void**)&p_g2, d_grid2);
    cudaGetSymbolAddress((void**)&p_wH1, d_wH1);
    cudaGetSymbolAddress((void**)&p_wH2, d_wH2);
    cudaGetSymbolAddress((void**)&p_be1, d_biasE1);
    cudaGetSymbolAddress((void**)&p_be2, d_biasE2);
    cudaGetSymbolAddress((void**)&p_cnt, d_cnt);

    cudaFuncSetAttribute(conv_tc_kernel, cudaFuncAttributeMaxDynamicSharedMemorySize, C_SMEM);

    fused_init_kernel<<<ZBLK + BATCH + 2 * PBLK, 256>>>(coords,                      // 1
        w1, b1, g1, be1, m1, v1, w2, b2, g2, be2, m2, v2);
    trans_scatter_kernel<<<dim3(NPTS / 32, 2, BATCH), dim3(32, 8)>>>(feats, coords); // 2
    conv_tc_kernel<<<BATCH * 128, 256, C_SMEM>>>(p_g0, p_g1, p_wH1, p_be1, p_cnt);   // 3
    conv_tc_kernel<<<BATCH * 128, 256, C_SMEM>>>(p_g1, p_g2, p_wH2, p_be2, nullptr); // 4 (ncu)
    devox_kernel<<<dim3(NPTS / 256, 17, BATCH), 256>>>(out, p_g2, coords);           // 5
}

// round 13
// speedup vs baseline: 1.1860x; 1.1860x over previous
#include <cuda_runtime.h>
#include <cuda_fp16.h>
#include <cstdint>

#define BATCH 8
#define CH 64
#define NPTS 65536
#define RR 32
#define NVOX 32768  // 32^3

// ---------------- scratch (__device__ globals; no allocation allowed) ------
__device__ float d_mean[BATCH * 3];
__device__ float d_scale[BATCH];
__device__ float d_voxc[BATCH * 3 * NPTS];            // clipped voxel coords
__device__ float d_cnt[BATCH * NVOX];                 // per-voxel point counts
__device__ float d_grid0[(size_t)BATCH * NVOX * CH];  // scatter SUMS (fp32)
__device__ __half d_gh1[(size_t)BATCH * NVOX * CH];   // after conv1 (fp16)
__device__ __half d_gh2[(size_t)BATCH * NVOX * CH];   // after conv2 (fp16)
// weights pre-shuffled into mma B-fragment order:
// uint32 index = ((tap*2+och)*8 + kc*2+half)*128 + lane*4 + nb
__device__ uint4 d_wF1[27 * 2 * 8 * 32];
__device__ uint4 d_wF2[27 * 2 * 8 * 32];
__device__ float d_biasE1[64];
__device__ float d_biasE2[64];

// ---------------- helpers ---------------------------------------------------
__device__ __forceinline__ unsigned h2_as_u32(__half2 h) {
    return *reinterpret_cast<unsigned*>(&h);
}
__device__ __forceinline__ void mma_f16(float& d0, float& d1, float& d2, float& d3,
                                        unsigned a0, unsigned a1, unsigned a2, unsigned a3,
                                        unsigned b0, unsigned b1) {
    asm("mma.sync.aligned.m16n8k16.row.col.f32.f16.f16.f32 "
        "{%0,%1,%2,%3},{%4,%5,%6,%7},{%8,%9},{%0,%1,%2,%3};"
        : "+f"(d0), "+f"(d1), "+f"(d2), "+f"(d3)
        : "r"(a0), "r"(a1), "r"(a2), "r"(a3), "r"(b0), "r"(b1));
}
__device__ __forceinline__ void ldsm_x4(unsigned& r0, unsigned& r1, unsigned& r2,
                                        unsigned& r3, uint32_t addr) {
    asm volatile("ldmatrix.sync.aligned.m8n8.x4.shared.b16 {%0,%1,%2,%3}, [%4];"
                 : "=r"(r0), "=r"(r1), "=r"(r2), "=r"(r3) : "r"(addr));
}

// ============ launch #1: fused zero + mean/scale + weight prep ==============
#define ZBLK 16640
#define WBLK 216   // 55296 uint32 weight-frag words per layer / 256
__global__ void fused_init_kernel(const float* __restrict__ coords,
                                  const float* __restrict__ w1, const float* __restrict__ b1,
                                  const float* __restrict__ g1, const float* __restrict__ be1,
                                  const float* __restrict__ m1, const float* __restrict__ v1,
                                  const float* __restrict__ w2, const float* __restrict__ b2,
                                  const float* __restrict__ g2, const float* __restrict__ be2,
                                  const float* __restrict__ m2, const float* __restrict__ v2) {
    __shared__ float red[3][256];
    int blk = blockIdx.x;
    int tid = threadIdx.x;

    if (blk < ZBLK) {
        size_t t = (size_t)blk * 256 + tid;
        const size_t g4 = (size_t)BATCH * NVOX * CH / 4;
        float4 z = make_float4(0.f, 0.f, 0.f, 0.f);
        if (t < g4) {
            reinterpret_cast<float4*>(d_grid0)[t] = z;
        } else {
            size_t u = t - g4;
            if (u < (size_t)BATCH * NVOX / 4) reinterpret_cast<float4*>(d_cnt)[u] = z;
        }
        return;
    }
    if (blk < ZBLK + BATCH) {
        int b = blk - ZBLK;
        const float* cb = coords + (size_t)b * 3 * NPTS;
        float s0 = 0.f, s1 = 0.f, s2 = 0.f;
        for (int n = tid; n < NPTS; n += 256) {
            s0 += cb[n];
            s1 += cb[NPTS + n];
            s2 += cb[2 * NPTS + n];
        }
        red[0][tid] = s0; red[1][tid] = s1; red[2][tid] = s2;
        __syncthreads();
        for (int off = 128; off > 0; off >>= 1) {
            if (tid < off) {
                red[0][tid] += red[0][tid + off];
                red[1][tid] += red[1][tid + off];
                red[2][tid] += red[2][tid + off];
            }
            __syncthreads();
        }
        float m0 = red[0][0] / (float)NPTS;
        float m1 = red[1][0] / (float)NPTS;
        float m2 = red[2][0] / (float)NPTS;
        __syncthreads();
        float mx = 0.f;
        for (int n = tid; n < NPTS; n += 256) {
            float dx = cb[n] - m0;
            float dy = cb[NPTS + n] - m1;
            float dz = cb[2 * NPTS + n] - m2;
            mx = fmaxf(mx, dx * dx + dy * dy + dz * dz);
        }
        red[0][tid] = mx;
        __syncthreads();
        for (int off = 128; off > 0; off >>= 1) {
            if (tid < off) red[0][tid] = fmaxf(red[0][tid], red[0][tid + off]);
            __syncthreads();
        }
        if (tid == 0) {
            d_mean[b * 3 + 0] = m0;
            d_mean[b * 3 + 1] = m1;
            d_mean[b * 3 + 2] = m2;
            d_scale[b] = sqrtf(red[0][0]);
        }
        return;
    }
    // weight prep: fragment-ordered fp16 weights + bias, BN folded
    const float *w, *bs, *g, *be, *m, *v;
    uint4* wF; float* biasE;
    int i;
    if (blk < ZBLK + BATCH + WBLK) {
        i = (blk - ZBLK - BATCH) * 256 + tid;
        w = w1; bs = b1; g = g1; be = be1; m = m1; v = v1;
        wF = d_wF1; biasE = d_biasE1;
    } else {
        i = (blk - ZBLK - BATCH - WBLK) * 256 + tid;
        w = w2; bs = b2; g = g2; be = be2; m = m2; v = v2;
        wF = d_wF2; biasE = d_biasE2;
    }
    if (i < 64) {
        float sc = g[i] * rsqrtf(v[i] + 1e-4f);
        biasE[i] = (bs[i] - m[i]) * sc + be[i];
    }
    // i in [0, 55296): one uint32 (half2) of the fragment layout
    {
        int nb = i & 3;
        int lane = (i >> 2) & 31;
        int half = (i >> 7) & 1;
        int kc = (i >> 8) & 3;
        int och = (i >> 10) & 1;
        int tap = i >> 11;
        if (tap < 27) {
            int oc = och * 32 + nb * 8 + (lane >> 2);
            int k0 = kc * 16 + half * 8 + 2 * (lane & 3);
            float sc = g[oc] * rsqrtf(v[oc] + 1e-4f);
            float v0 = w[(oc * 64 + k0) * 27 + tap] * sc;
            float v1 = w[(oc * 64 + k0 + 1) * 27 + tap] * sc;
            reinterpret_cast<unsigned*>(wF)[
                (((tap * 2 + och) * 8 + kc * 2 + half) << 7) + lane * 4 + nb] =
                h2_as_u32(__floats2half2_rn(v0, v1));
        }
    }
}

// ============ launch #2: transpose-scatter (+ inline voxelize) ==============
__global__ void trans_scatter_kernel(const float* __restrict__ f,
                                     const float* __restrict__ coords) {
    __shared__ float tile[32][33];     // [c][n]
    int b = blockIdx.z;
    int c0 = blockIdx.y * 32;
    int n0 = blockIdx.x * 32;
    int tx = threadIdx.x, ty = threadIdx.y;
    const float* fb = f + (size_t)b * CH * NPTS;
#pragma unroll
    for (int i = 0; i < 4; i++) {
        int c = c0 + ty + i * 8;
        tile[ty + i * 8][tx] = fb[(size_t)c * NPTS + n0 + tx];
    }
    __syncthreads();
    int n = n0 + tx;
    const float* cb = coords + (size_t)b * 3 * NPTS;
    float m0 = d_mean[b * 3 + 0], m1 = d_mean[b * 3 + 1], m2 = d_mean[b * 3 + 2];
    float den = d_scale[b] * 2.0f;
    float vx = fminf(fmaxf(((cb[n]            - m0) / den + 0.5f) * 32.0f, 0.f), 31.f);
    float vy = fminf(fmaxf(((cb[NPTS + n]     - m1) / den + 0.5f) * 32.0f, 0.f), 31.f);
    float vz = fminf(fmaxf(((cb[2 * NPTS + n] - m2) / den + 0.5f) * 32.0f, 0.f), 31.f);
    int idx = (((int)rintf(vx)) * 32 + (int)rintf(vy)) * 32 + (int)rintf(vz);
    if (blockIdx.y == 0 && ty == 0) {
        float* vout = d_voxc + (size_t)b * 3 * NPTS;
        vout[n] = vx;
        vout[NPTS + n] = vy;
        vout[2 * NPTS + n] = vz;
        atomicAdd(&d_cnt[b * NVOX + idx], 1.0f);
    }
    float* gb = &d_grid0[((size_t)b * NVOX + idx) * CH + c0 + ty * 4];
    float v0 = tile[ty * 4 + 0][tx];
    float v1 = tile[ty * 4 + 1][tx];
    float v2 = tile[ty * 4 + 2][tx];
    float v3 = tile[ty * 4 + 3][tx];
    asm volatile("red.global.add.v4.f32 [%0], {%1, %2, %3, %4};"
                 :: "l"(gb), "f"(v0), "f"(v1), "f"(v2), "f"(v3) : "memory");
}

// ============ launches #3/#4: conv — fp16 HMMA, ZERO mainloop barriers ======
// Tile 4x8x8 = 256 vox, 256 threads (8 warps), warp = m64 x n32, K=64/tap.
// Halo 6x10x10 rows x 128B fp16, XOR-swizzled, read-only after one barrier.
// Weights fetched per-tap via 8 coalesced LDG.128 in fragment order (L2-hot).
// conv1 (IN_HALF=false) reads fp32 sums + fuses 1/cnt; conv2 reads fp16.
#define C_HROWS 600
#define C_INH (C_HROWS * 64)              // 38400 halfs
#define C_SMEM (C_INH * 2)                // 76800 bytes (halo only)

template <bool IN_HALF>
__global__ void __launch_bounds__(256, 2) conv_tc_kernel(const void* __restrict__ gin_,
                                                         __half* __restrict__ gout,
                                                         const uint4* __restrict__ wF,
                                                         const float* __restrict__ biasE,
                                                         const float* __restrict__ cnt) {
    extern __shared__ __half shh[];
    __half* in_sh = shh;
    uint32_t insh_u32 = (uint32_t)__cvta_generic_to_shared(in_sh);

    int tid = threadIdx.x;
    int bx = blockIdx.x;
    int b = bx >> 7;                       // 128 tiles/batch
    int tile = bx & 127;
    int x0 = (tile >> 4) * 4;
    int y0 = ((tile >> 2) & 3) * 8;
    int z0 = (tile & 3) * 8;

    // halo: 600 rows x 128B fp16, zero-pad, XOR-swizzled (chunk c -> c^(row&7))
    for (int s = tid; s < C_HROWS * 8; s += 256) {
        int vox = s >> 3, c8 = s & 7;
        int hx = vox / 100;
        int r = vox - hx * 100;
        int hy = r / 10;
        int hz = r - hy * 10;
        int gx = x0 + hx - 1, gy = y0 + hy - 1, gz = z0 + hz - 1;
        uint4 pk = make_uint4(0u, 0u, 0u, 0u);
        if ((unsigned)gx < 32u && (unsigned)gy < 32u && (unsigned)gz < 32u) {
            size_t gvox = (((size_t)b * 32 + gx) * 32 + gy) * 32 + gz;
            if (IN_HALF) {
                pk = *reinterpret_cast<const uint4*>(
                    &((const __half*)gin_)[gvox * CH + c8 * 8]);
            } else {
                const float4* src = reinterpret_cast<const float4*>(
                    &((const float*)gin_)[gvox * CH + c8 * 8]);
                float4 lo = src[0];
                float4 hi = src[1];
                float inv = 1.0f / fmaxf(cnt[gvox], 1.0f);
                lo.x *= inv; lo.y *= inv; lo.z *= inv; lo.w *= inv;
                hi.x *= inv; hi.y *= inv; hi.z *= inv; hi.w *= inv;
                pk.x = h2_as_u32(__floats2half2_rn(lo.x, lo.y));
                pk.y = h2_as_u32(__floats2half2_rn(lo.z, lo.w));
                pk.z = h2_as_u32(__floats2half2_rn(hi.x, hi.y));
                pk.w = h2_as_u32(__floats2half2_rn(hi.z, hi.w));
            }
        }
        *reinterpret_cast<uint4*>(in_sh + vox * 64 + ((c8 ^ (vox & 7)) << 3)) = pk;
    }
    __syncthreads();                       // the ONLY barrier

    int w = tid >> 5;                      // warp [0,8)
    int lane = tid & 31;
    int g = w >> 1;                        // voxel group: x = x0 + g
    int och = w & 1;                       // oc half (n32)
    int yq = (lane >> 3) & 1;
    int lr = lane & 7;
    int kh = lane >> 4;

    int aRow0[4];
#pragma unroll
    for (int i = 0; i < 4; i++) aRow0[i] = g * 100 + (2 * i + yq) * 10 + lr;

    float acc[4][4][4];
#pragma unroll
    for (int i = 0; i < 4; i++)
#pragma unroll
        for (int nb = 0; nb < 4; nb++)
#pragma unroll
            for (int j = 0; j < 4; j++) acc[i][nb][j] = 0.f;

    for (int tap = 0; tap < 27; tap++) {
        int dxi = tap / 9;
        int rr9 = tap - dxi * 9;
        int dyi = rr9 / 3;
        int dzi = rr9 - dyi * 3;
        int dr = dxi * 100 + dyi * 10 + dzi;

        uint32_t aAddr[4];
        int asw[4];
#pragma unroll
        for (int i = 0; i < 4; i++) {
            int rr = aRow0[i] + dr;
            aAddr[i] = insh_u32 + ((uint32_t)rr << 7);
            asw[i] = (rr & 7) << 4;
        }
        // per-lane fragment-ordered weights: 8 coalesced LDG.128 this tap
        const uint4* wt = wF + (((tap * 2 + och) * 8) << 5) + lane;

#pragma unroll
        for (int kc = 0; kc < 4; kc++) {
            uint4 q0 = wt[(kc * 2 + 0) << 5];   // b0 of nb0..3
            uint4 q1 = wt[(kc * 2 + 1) << 5];   // b1 of nb0..3
            int ck = (kc * 2 + kh) << 4;
            unsigned A[4][4];
#pragma unroll
            for (int i = 0; i < 4; i++)
                ldsm_x4(A[i][0], A[i][1], A[i][2], A[i][3],
                        aAddr[i] + (uint32_t)(ck ^ asw[i]));
#pragma unroll
            for (int i = 0; i < 4; i++) {
                mma_f16(acc[i][0][0], acc[i][0][1], acc[i][0][2], acc[i][0][3],
                        A[i][0], A[i][1], A[i][2], A[i][3], q0.x, q1.x);
                mma_f16(acc[i][1][0], acc[i][1][1], acc[i][1][2], acc[i][1][3],
                        A[i][0], A[i][1], A[i][2], A[i][3], q0.y, q1.y);
                mma_f16(acc[i][2][0], acc[i][2][1], acc[i][2][2], acc[i][2][3],
                        A[i][0], A[i][1], A[i][2], A[i][3], q0.z, q1.z);
                mma_f16(acc[i][3][0], acc[i][3][1], acc[i][3][2], acc[i][3][3],
                        A[i][0], A[i][1], A[i][2], A[i][3], q0.w, q1.w);
            }
        }
    }

    // epilogue: fp16 output. tile i -> y = y0+2i (c0/c1), y0+2i+1 (c2/c3)
    int zq = lane >> 2;
    int kq = lane & 3;
    int X = x0 + g;
    int Z = z0 + zq;
#pragma unroll
    for (int i = 0; i < 4; i++) {
        size_t base_lo = ((((size_t)b * 32 + X) * 32 + (y0 + 2 * i)) * 32 + Z) * CH;
        size_t base_hi = base_lo + 32 * CH;
#pragma unroll
        for (int nb = 0; nb < 4; nb++) {
            int oc = och * 32 + nb * 8 + 2 * kq;
            float2 bb = *reinterpret_cast<const float2*>(&biasE[oc]);
            float y00 = acc[i][nb][0] + bb.x;
            float y01 = acc[i][nb][1] + bb.y;
            float y10 = acc[i][nb][2] + bb.x;
            float y11 = acc[i][nb][3] + bb.y;
            y00 = (y00 >= 0.f) ? y00 : 0.1f * y00;
            y01 = (y01 >= 0.f) ? y01 : 0.1f * y01;
            y10 = (y10 >= 0.f) ? y10 : 0.1f * y10;
            y11 = (y11 >= 0.f) ? y11 : 0.1f * y11;
            *reinterpret_cast<__half2*>(&gout[base_lo + oc]) = __floats2half2_rn(y00, y01);
            *reinterpret_cast<__half2*>(&gout[base_hi + oc]) = __floats2half2_rn(y10, y11);
        }
    }
}

// ============ launch #5: trilinear devoxelize fp16 (+ coords echo) ==========
// grid (NPTS/256, 9, BATCH): cg<8 -> 8 channels each; cg==8 -> coords echo.
__global__ void devox_kernel(float* __restrict__ out, const __half* __restrict__ grid,
                             const float* __restrict__ coords) {
    int n = blockIdx.x * 256 + threadIdx.x;
    int cg = blockIdx.y;
    int b = blockIdx.z;
    if (cg == 8) {   // coords echo
        float* out2 = out + (size_t)BATCH * CH * NPTS;
        size_t base = (size_t)b * 3 * NPTS;
        out2[base + n] = coords[base + n];
        out2[base + NPTS + n] = coords[base + NPTS + n];
        out2[base + 2 * NPTS + n] = coords[base + 2 * NPTS + n];
        return;
    }
    const float* vc = d_voxc + (size_t)b * 3 * NPTS;
    float cx = vc[n], cy = vc[NPTS + n], cz = vc[2 * NPTS + n];
    int ix0 = (int)floorf(cx), iy0 = (int)floorf(cy), iz0 = (int)floorf(cz);
    float fx = cx - (float)ix0, fy = cy - (float)iy0, fz = cz - (float)iz0;
    int ix1 = min(ix0 + 1, 31), iy1 = min(iy0 + 1, 31), iz1 = min(iz0 + 1, 31);
    float gx0 = 1.f - fx, gy0 = 1.f - fy, gz0 = 1.f - fz;

    const __half* g = grid + ((size_t)b * NVOX) * CH + cg * 8;
    float acc8[8];
#pragma unroll
    for (int j = 0; j < 8; j++) acc8[j] = 0.f;

#define CORNER(XI, YI, ZI, W)                                                        \
    {                                                                                \
        uint4 raw = *reinterpret_cast<const uint4*>(                                 \
            &g[(size_t)(((XI) * 32 + (YI)) * 32 + (ZI)) * CH]);                      \
        const __half2* hp = reinterpret_cast<const __half2*>(&raw);                  \
        float ww = (W);                                                              \
        _Pragma("unroll")                                                            \
        for (int j = 0; j < 4; j++) {                                                \
            float2 f2 = __half22float2(hp[j]);                                       \
            acc8[2 * j] += ww * f2.x;                                                \
            acc8[2 * j + 1] += ww * f2.y;                                            \
        }                                                                            \
    }
    CORNER(ix0, iy0, iz0, gx0 * gy0 * gz0)
    CORNER(ix0, iy0, iz1, gx0 * gy0 * fz)
    CORNER(ix0, iy1, iz0, gx0 * fy * gz0)
    CORNER(ix0, iy1, iz1, gx0 * fy * fz)
    CORNER(ix1, iy0, iz0, fx * gy0 * gz0)
    CORNER(ix1, iy0, iz1, fx * gy0 * fz)
    CORNER(ix1, iy1, iz0, fx * fy * gz0)
    CORNER(ix1, iy1, iz1, fx * fy * fz)
#undef CORNER

    size_t ob = ((size_t)b * CH + cg * 8) * NPTS + n;
#pragma unroll
    for (int j = 0; j < 8; j++) out[ob + (size_t)j * NPTS] = acc8[j];
}

// ---------------- launch ----------------------------------------------------
extern "C" void kernel_launch(void* const* d_in, const int* in_sizes, int n_in,
                              void* d_out, int out_size) {
    (void)in_sizes; (void)n_in; (void)out_size;
    const float* feats  = (const float*)d_in[0];
    const float* coords = (const float*)d_in[1];
    const float* w1  = (const float*)d_in[2];
    const float* b1  = (const float*)d_in[3];
    const float* g1  = (const float*)d_in[4];
    const float* be1 = (const float*)d_in[5];
    const float* m1  = (const float*)d_in[6];
    const float* v1  = (const float*)d_in[7];
    const float* w2  = (const float*)d_in[8];
    const float* b2  = (const float*)d_in[9];
    const float* g2  = (const float*)d_in[10];
    const float* be2 = (const float*)d_in[11];
    const float* m2  = (const float*)d_in[12];
    const float* v2  = (const float*)d_in[13];
    float* out = (float*)d_out;

    float *p_g0, *p_be1, *p_be2, *p_cnt;
    __half *p_gh1, *p_gh2;
    uint4 *p_wF1, *p_wF2;
    cudaGetSymbolAddress((void**)&p_g0, d_grid0);
    cudaGetSymbolAddress((void**)&p_gh1, d_gh1);
    cudaGetSymbolAddress((void**)&p_gh2, d_gh2);
    cudaGetSymbolAddress((void**)&p_wF1, d_wF1);
    cudaGetSymbolAddress((void**)&p_wF2, d_wF2);
    cudaGetSymbolAddress((void**)&p_be1, d_biasE1);
    cudaGetSymbolAddress((void**)&p_be2, d_biasE2);
    cudaGetSymbolAddress((void**)&p_cnt, d_cnt);

    cudaFuncSetAttribute(conv_tc_kernel<false>,
                         cudaFuncAttributeMaxDynamicSharedMemorySize, C_SMEM);
    cudaFuncSetAttribute(conv_tc_kernel<true>,
                         cudaFuncAttributeMaxDynamicSharedMemorySize, C_SMEM);

    fused_init_kernel<<<ZBLK + BATCH + 2 * WBLK, 256>>>(coords,                      // 1
        w1, b1, g1, be1, m1, v1, w2, b2, g2, be2, m2, v2);
    trans_scatter_kernel<<<dim3(NPTS / 32, 2, BATCH), dim3(32, 8)>>>(feats, coords); // 2
    conv_tc_kernel<false><<<BATCH * 128, 256, C_SMEM>>>(p_g0, p_gh1, p_wF1,          // 3
                                                        p_be1, p_cnt);
    conv_tc_kernel<true><<<BATCH * 128, 256, C_SMEM>>>(p_gh1, p_gh2, p_wF2,          // 4 (ncu)
                                                       p_be2, nullptr);
    devox_kernel<<<dim3(NPTS / 256, 9, BATCH), 256>>>(out, p_gh2, coords);           // 5
}

// round 15
// speedup vs baseline: 1.3079x; 1.1028x over previous
#include <cuda_runtime.h>
#include <cuda_fp16.h>
#include <cstdint>

#define BATCH 8
#define CH 64
#define NPTS 65536
#define RR 32
#define NVOX 32768  // 32^3

// ---------------- scratch (__device__ globals; no allocation allowed) ------
__device__ float d_meanAcc[BATCH * 3];                // sum accumulators (re-zeroed by devox)
__device__ unsigned d_scaleAcc[BATCH];                // max(|x-mean|^2) as uint bits
__device__ float d_voxc[BATCH * 3 * NPTS];            // clipped voxel coords
__device__ float d_cnt[BATCH * NVOX];                 // per-voxel point counts
__device__ float d_grid0[(size_t)BATCH * NVOX * CH];  // scatter SUMS (fp32)
__device__ __half d_gh1[(size_t)BATCH * NVOX * CH];   // after conv1 (fp16)
__device__ __half d_gh2[(size_t)BATCH * NVOX * CH];   // after conv2 (fp16)
// weights pre-shuffled into mma B-fragment order:
// uint32 index = ((tap*2+och)*8 + kc*2+half)*128 + lane*4 + nb
__device__ uint4 d_wF1[27 * 2 * 8 * 32];
__device__ uint4 d_wF2[27 * 2 * 8 * 32];
__device__ float d_biasE1[64];
__device__ float d_biasE2[64];

// ---------------- helpers ---------------------------------------------------
__device__ __forceinline__ unsigned h2_as_u32(__half2 h) {
    return *reinterpret_cast<unsigned*>(&h);
}
__device__ __forceinline__ void mma_f16(float& d0, float& d1, float& d2, float& d3,
                                        unsigned a0, unsigned a1, unsigned a2, unsigned a3,
                                        unsigned b0, unsigned b1) {
    asm("mma.sync.aligned.m16n8k16.row.col.f32.f16.f16.f32 "
        "{%0,%1,%2,%3},{%4,%5,%6,%7},{%8,%9},{%0,%1,%2,%3};"
        : "+f"(d0), "+f"(d1), "+f"(d2), "+f"(d3)
        : "r"(a0), "r"(a1), "r"(a2), "r"(a3), "r"(b0), "r"(b1));
}
__device__ __forceinline__ void ldsm_x4(unsigned& r0, unsigned& r1, unsigned& r2,
                                        unsigned& r3, uint32_t addr) {
    asm volatile("ldmatrix.sync.aligned.m8n8.x4.shared.b16 {%0,%1,%2,%3}, [%4];"
                 : "=r"(r0), "=r"(r1), "=r"(r2), "=r"(r3) : "r"(addr));
}

// ============ launch #1: zero + weight prep + mean partials =================
#define ZBLK 16640
#define WBLK 216   // 55296 uint32 weight-frag words per layer / 256
#define MBLK 512   // 64 mean-partial blocks per batch
__global__ void fused_init_kernel(const float* __restrict__ coords,
                                  const float* __restrict__ w1, const float* __restrict__ b1,
                                  const float* __restrict__ g1, const float* __restrict__ be1,
                                  const float* __restrict__ m1, const float* __restrict__ v1,
                                  const float* __restrict__ w2, const float* __restrict__ b2,
                                  const float* __restrict__ g2, const float* __restrict__ be2,
                                  const float* __restrict__ m2, const float* __restrict__ v2) {
    __shared__ float red[3][256];
    int blk = blockIdx.x;
    int tid = threadIdx.x;

    if (blk < ZBLK) {
        size_t t = (size_t)blk * 256 + tid;
        const size_t g4 = (size_t)BATCH * NVOX * CH / 4;
        float4 z = make_float4(0.f, 0.f, 0.f, 0.f);
        if (t < g4) {
            reinterpret_cast<float4*>(d_grid0)[t] = z;
        } else {
            size_t u = t - g4;
            if (u < (size_t)BATCH * NVOX / 4) reinterpret_cast<float4*>(d_cnt)[u] = z;
        }
        return;
    }
    if (blk < ZBLK + 2 * WBLK) {
        // weight prep: fragment-ordered fp16 weights + bias, BN folded
        const float *w, *bs, *g, *be, *m, *v;
        uint4* wF; float* biasE;
        int i;
        if (blk < ZBLK + WBLK) {
            i = (blk - ZBLK) * 256 + tid;
            w = w1; bs = b1; g = g1; be = be1; m = m1; v = v1;
            wF = d_wF1; biasE = d_biasE1;
        } else {
            i = (blk - ZBLK - WBLK) * 256 + tid;
            w = w2; bs = b2; g = g2; be = be2; m = m2; v = v2;
            wF = d_wF2; biasE = d_biasE2;
        }
        if (i < 64) {
            float sc = g[i] * rsqrtf(v[i] + 1e-4f);
            biasE[i] = (bs[i] - m[i]) * sc + be[i];
        }
        int nb = i & 3;
        int lane = (i >> 2) & 31;
        int half = (i >> 7) & 1;
        int kc = (i >> 8) & 3;
        int och = (i >> 10) & 1;
        int tap = i >> 11;
        if (tap < 27) {
            int oc = och * 32 + nb * 8 + (lane >> 2);
            int k0 = kc * 16 + half * 8 + 2 * (lane & 3);
            float sc = g[oc] * rsqrtf(v[oc] + 1e-4f);
            float v0 = w[(oc * 64 + k0) * 27 + tap] * sc;
            float v1 = w[(oc * 64 + k0 + 1) * 27 + tap] * sc;
            reinterpret_cast<unsigned*>(wF)[
                (((tap * 2 + och) * 8 + kc * 2 + half) << 7) + lane * 4 + nb] =
                h2_as_u32(__floats2half2_rn(v0, v1));
        }
        return;
    }
    // mean partial sums: 64 blocks per batch, atomicAdd into d_meanAcc
    {
        int t = blk - (ZBLK + 2 * WBLK);   // [0, 512)
        int b = t >> 6;
        int base = (t & 63) * 1024;
        const float* cb = coords + (size_t)b * 3 * NPTS;
        float s0 = 0.f, s1 = 0.f, s2 = 0.f;
        for (int i = tid; i < 1024; i += 256) {
            int n = base + i;
            s0 += cb[n];
            s1 += cb[NPTS + n];
            s2 += cb[2 * NPTS + n];
        }
        red[0][tid] = s0; red[1][tid] = s1; red[2][tid] = s2;
        __syncthreads();
        for (int off = 128; off > 0; off >>= 1) {
            if (tid < off) {
                red[0][tid] += red[0][tid + off];
                red[1][tid] += red[1][tid + off];
                red[2][tid] += red[2][tid + off];
            }
            __syncthreads();
        }
        if (tid == 0) {
            atomicAdd(&d_meanAcc[b * 3 + 0], red[0][0]);
            atomicAdd(&d_meanAcc[b * 3 + 1], red[1][0]);
            atomicAdd(&d_meanAcc[b * 3 + 2], red[2][0]);
        }
        return;
    }
}

// ============ launch #2: scale partials (max |x-mean|^2, atomicMax) =========
__global__ void scale_kernel(const float* __restrict__ coords) {
    __shared__ float red[256];
    int blk = blockIdx.x;                  // [0, 512)
    int tid = threadIdx.x;
    int b = blk >> 6;
    int base = (blk & 63) * 1024;
    const float* cb = coords + (size_t)b * 3 * NPTS;
    float inv = 1.0f / (float)NPTS;
    float m0 = d_meanAcc[b * 3 + 0] * inv;
    float m1 = d_meanAcc[b * 3 + 1] * inv;
    float m2 = d_meanAcc[b * 3 + 2] * inv;
    float mx = 0.f;
    for (int i = tid; i < 1024; i += 256) {
        int n = base + i;
        float dx = cb[n] - m0;
        float dy = cb[NPTS + n] - m1;
        float dz = cb[2 * NPTS + n] - m2;
        mx = fmaxf(mx, dx * dx + dy * dy + dz * dz);
    }
    red[tid] = mx;
    __syncthreads();
    for (int off = 128; off > 0; off >>= 1) {
        if (tid < off) red[tid] = fmaxf(red[tid], red[tid + off]);
        __syncthreads();
    }
    if (tid == 0) atomicMax(&d_scaleAcc[b], __float_as_uint(red[0]));
}

// ============ launch #3: transpose-scatter (+ inline voxelize) ==============
__global__ void trans_scatter_kernel(const float* __restrict__ f,
                                     const float* __restrict__ coords) {
    __shared__ float tile[32][33];     // [c][n]
    int b = blockIdx.z;
    int c0 = blockIdx.y * 32;
    int n0 = blockIdx.x * 32;
    int tx = threadIdx.x, ty = threadIdx.y;
    const float* fb = f + (size_t)b * CH * NPTS;
#pragma unroll
    for (int i = 0; i < 4; i++) {
        int c = c0 + ty + i * 8;
        tile[ty + i * 8][tx] = fb[(size_t)c * NPTS + n0 + tx];
    }
    __syncthreads();
    int n = n0 + tx;
    const float* cb = coords + (size_t)b * 3 * NPTS;
    float inv = 1.0f / (float)NPTS;
    float m0 = d_meanAcc[b * 3 + 0] * inv;
    float m1 = d_meanAcc[b * 3 + 1] * inv;
    float m2 = d_meanAcc[b * 3 + 2] * inv;
    float den = sqrtf(__uint_as_float(d_scaleAcc[b])) * 2.0f;
    float vx = fminf(fmaxf(((cb[n]            - m0) / den + 0.5f) * 32.0f, 0.f), 31.f);
    float vy = fminf(fmaxf(((cb[NPTS + n]     - m1) / den + 0.5f) * 32.0f, 0.f), 31.f);
    float vz = fminf(fmaxf(((cb[2 * NPTS + n] - m2) / den + 0.5f) * 32.0f, 0.f), 31.f);
    int idx = (((int)rintf(vx)) * 32 + (int)rintf(vy)) * 32 + (int)rintf(vz);
    if (blockIdx.y == 0 && ty == 0) {
        float* vout = d_voxc + (size_t)b * 3 * NPTS;
        vout[n] = vx;
        vout[NPTS + n] = vy;
        vout[2 * NPTS + n] = vz;
        atomicAdd(&d_cnt[b * NVOX + idx], 1.0f);
    }
    float* gb = &d_grid0[((size_t)b * NVOX + idx) * CH + c0 + ty * 4];
    float v0 = tile[ty * 4 + 0][tx];
    float v1 = tile[ty * 4 + 1][tx];
    float v2 = tile[ty * 4 + 2][tx];
    float v3 = tile[ty * 4 + 3][tx];
    asm volatile("red.global.add.v4.f32 [%0], {%1, %2, %3, %4};"
                 :: "l"(gb), "f"(v0), "f"(v1), "f"(v2), "f"(v3) : "memory");
}

// ============ launches #4/#5: conv — fp16 HMMA, ZERO mainloop barriers ======
// Tile 4x8x8 = 256 vox, 256 threads (8 warps), warp = m64 x n32, K=64/tap.
// Halo 6x10x10 rows x 128B fp16, XOR-swizzled, read-only after one barrier.
// Weights fetched per-tap via 8 coalesced LDG.128 in fragment order (L2-hot).
// conv1 (IN_HALF=false) reads fp32 sums + fuses 1/cnt; conv2 reads fp16.
#define C_HROWS 600
#define C_INH (C_HROWS * 64)              // 38400 halfs
#define C_SMEM (C_INH * 2)                // 76800 bytes (halo only)

template <bool IN_HALF>
__global__ void __launch_bounds__(256, 2) conv_tc_kernel(const void* __restrict__ gin_,
                                                         __half* __restrict__ gout,
                                                         const uint4* __restrict__ wF,
                                                         const float* __restrict__ biasE,
                                                         const float* __restrict__ cnt) {
    extern __shared__ __half shh[];
    __half* in_sh = shh;
    uint32_t insh_u32 = (uint32_t)__cvta_generic_to_shared(in_sh);

    int tid = threadIdx.x;
    int bx = blockIdx.x;
    int b = bx >> 7;                       // 128 tiles/batch
    int tile = bx & 127;
    int x0 = (tile >> 4) * 4;
    int y0 = ((tile >> 2) & 3) * 8;
    int z0 = (tile & 3) * 8;

    // halo: 600 rows x 128B fp16, zero-pad, XOR-swizzled (chunk c -> c^(row&7))
    for (int s = tid; s < C_HROWS * 8; s += 256) {
        int vox = s >> 3, c8 = s & 7;
        int hx = vox / 100;
        int r = vox - hx * 100;
        int hy = r / 10;
        int hz = r - hy * 10;
        int gx = x0 + hx - 1, gy = y0 + hy - 1, gz = z0 + hz - 1;
        uint4 pk = make_uint4(0u, 0u, 0u, 0u);
        if ((unsigned)gx < 32u && (unsigned)gy < 32u && (unsigned)gz < 32u) {
            size_t gvox = (((size_t)b * 32 + gx) * 32 + gy) * 32 + gz;
            if (IN_HALF) {
                pk = *reinterpret_cast<const uint4*>(
                    &((const __half*)gin_)[gvox * CH + c8 * 8]);
            } else {
                const float4* src = reinterpret_cast<const float4*>(
                    &((const float*)gin_)[gvox * CH + c8 * 8]);
                float4 lo = src[0];
                float4 hi = src[1];
                float inv = 1.0f / fmaxf(cnt[gvox], 1.0f);
                lo.x *= inv; lo.y *= inv; lo.z *= inv; lo.w *= inv;
                hi.x *= inv; hi.y *= inv; hi.z *= inv; hi.w *= inv;
                pk.x = h2_as_u32(__floats2half2_rn(lo.x, lo.y));
                pk.y = h2_as_u32(__floats2half2_rn(lo.z, lo.w));
                pk.z = h2_as_u32(__floats2half2_rn(hi.x, hi.y));
                pk.w = h2_as_u32(__floats2half2_rn(hi.z, hi.w));
            }
        }
        *reinterpret_cast<uint4*>(in_sh + vox * 64 + ((c8 ^ (vox & 7)) << 3)) = pk;
    }
    __syncthreads();                       // the ONLY barrier

    int w = tid >> 5;                      // warp [0,8)
    int lane = tid & 31;
    int g = w >> 1;                        // voxel group: x = x0 + g
    int och = w & 1;                       // oc half (n32)
    int yq = (lane >> 3) & 1;
    int lr = lane & 7;
    int kh = lane >> 4;

    int aRow0[4];
#pragma unroll
    for (int i = 0; i < 4; i++) aRow0[i] = g * 100 + (2 * i + yq) * 10 + lr;

    float acc[4][4][4];
#pragma unroll
    for (int i = 0; i < 4; i++)
#pragma unroll
        for (int nb = 0; nb < 4; nb++)
#pragma unroll
            for (int j = 0; j < 4; j++) acc[i][nb][j] = 0.f;

    for (int tap = 0; tap < 27; tap++) {
        int dxi = tap / 9;
        int rr9 = tap - dxi * 9;
        int dyi = rr9 / 3;
        int dzi = rr9 - dyi * 3;
        int dr = dxi * 100 + dyi * 10 + dzi;

        uint32_t aAddr[4];
        int asw[4];
#pragma unroll
        for (int i = 0; i < 4; i++) {
            int rr = aRow0[i] + dr;
            aAddr[i] = insh_u32 + ((uint32_t)rr << 7);
            asw[i] = (rr & 7) << 4;
        }
        const uint4* wt = wF + (((tap * 2 + och) * 8) << 5) + lane;

#pragma unroll
        for (int kc = 0; kc < 4; kc++) {
            uint4 q0 = wt[(kc * 2 + 0) << 5];   // b0 of nb0..3
            uint4 q1 = wt[(kc * 2 + 1) << 5];   // b1 of nb0..3
            int ck = (kc * 2 + kh) << 4;
            unsigned A[4][4];
#pragma unroll
            for (int i = 0; i < 4; i++)
                ldsm_x4(A[i][0], A[i][1], A[i][2], A[i][3],
                        aAddr[i] + (uint32_t)(ck ^ asw[i]));
#pragma unroll
            for (int i = 0; i < 4; i++) {
                mma_f16(acc[i][0][0], acc[i][0][1], acc[i][0][2], acc[i][0][3],
                        A[i][0], A[i][1], A[i][2], A[i][3], q0.x, q1.x);
                mma_f16(acc[i][1][0], acc[i][1][1], acc[i][1][2], acc[i][1][3],
                        A[i][0], A[i][1], A[i][2], A[i][3], q0.y, q1.y);
                mma_f16(acc[i][2][0], acc[i][2][1], acc[i][2][2], acc[i][2][3],
                        A[i][0], A[i][1], A[i][2], A[i][3], q0.z, q1.z);
                mma_f16(acc[i][3][0], acc[i][3][1], acc[i][3][2], acc[i][3][3],
                        A[i][0], A[i][1], A[i][2], A[i][3], q0.w, q1.w);
            }
        }
    }

    // epilogue: fp16 output. tile i -> y = y0+2i (c0/c1), y0+2i+1 (c2/c3)
    int zq = lane >> 2;
    int kq = lane & 3;
    int X = x0 + g;
    int Z = z0 + zq;
#pragma unroll
    for (int i = 0; i < 4; i++) {
        size_t base_lo = ((((size_t)b * 32 + X) * 32 + (y0 + 2 * i)) * 32 + Z) * CH;
        size_t base_hi = base_lo + 32 * CH;
#pragma unroll
        for (int nb = 0; nb < 4; nb++) {
            int oc = och * 32 + nb * 8 + 2 * kq;
            float2 bb = *reinterpret_cast<const float2*>(&biasE[oc]);
            float y00 = acc[i][nb][0] + bb.x;
            float y01 = acc[i][nb][1] + bb.y;
            float y10 = acc[i][nb][2] + bb.x;
            float y11 = acc[i][nb][3] + bb.y;
            y00 = (y00 >= 0.f) ? y00 : 0.1f * y00;
            y01 = (y01 >= 0.f) ? y01 : 0.1f * y01;
            y10 = (y10 >= 0.f) ? y10 : 0.1f * y10;
            y11 = (y11 >= 0.f) ? y11 : 0.1f * y11;
            *reinterpret_cast<__half2*>(&gout[base_lo + oc]) = __floats2half2_rn(y00, y01);
            *reinterpret_cast<__half2*>(&gout[base_hi + oc]) = __floats2half2_rn(y10, y11);
        }
    }
}

// ============ launch #6: devoxelize fp16 + coords echo + accum re-zero ======
__global__ void devox_kernel(float* __restrict__ out, const __half* __restrict__ grid,
                             const float* __restrict__ coords) {
    int n = blockIdx.x * 256 + threadIdx.x;
    int cg = blockIdx.y;
    int b = blockIdx.z;
    if (cg == 8) {   // coords echo (+ re-zero reduction accumulators for next replay)
        if (blockIdx.x == 0 && b == 0) {
            int t = threadIdx.x;
            if (t < BATCH * 3) d_meanAcc[t] = 0.f;
            if (t < BATCH) d_scaleAcc[t] = 0u;
        }
        float* out2 = out + (size_t)BATCH * CH * NPTS;
        size_t base = (size_t)b * 3 * NPTS;
        out2[base + n] = coords[base + n];
        out2[base + NPTS + n] = coords[base + NPTS + n];
        out2[base + 2 * NPTS + n] = coords[base + 2 * NPTS + n];
        return;
    }
    const float* vc = d_voxc + (size_t)b * 3 * NPTS;
    float cx = vc[n], cy = vc[NPTS + n], cz = vc[2 * NPTS + n];
    int ix0 = (int)floorf(cx), iy0 = (int)floorf(cy), iz0 = (int)floorf(cz);
    float fx = cx - (float)ix0, fy = cy - (float)iy0, fz = cz - (float)iz0;
    int ix1 = min(ix0 + 1, 31), iy1 = min(iy0 + 1, 31), iz1 = min(iz0 + 1, 31);
    float gx0 = 1.f - fx, gy0 = 1.f - fy, gz0 = 1.f - fz;

    const __half* g = grid + ((size_t)b * NVOX) * CH + cg * 8;
    float acc8[8];
#pragma unroll
    for (int j = 0; j < 8; j++) acc8[j] = 0.f;

#define CORNER(XI, YI, ZI, W)                                                        \
    {                                                                                \
        uint4 raw = *reinterpret_cast<const uint4*>(                                 \
            &g[(size_t)(((XI) * 32 + (YI)) * 32 + (ZI)) * CH]);                      \
        const __half2* hp = reinterpret_cast<const __half2*>(&raw);                  \
        float ww = (W);                                                              \
        _Pragma("unroll")                                                            \
        for (int j = 0; j < 4; j++) {                                                \
            float2 f2 = __half22float2(hp[j]);                                       \
            acc8[2 * j] += ww * f2.x;                                                \
            acc8[2 * j + 1] += ww * f2.y;                                            \
        }                                                                            \
    }
    CORNER(ix0, iy0, iz0, gx0 * gy0 * gz0)
    CORNER(ix0, iy0, iz1, gx0 * gy0 * fz)
    CORNER(ix0, iy1, iz0, gx0 * fy * gz0)
    CORNER(ix0, iy1, iz1, gx0 * fy * fz)
    CORNER(ix1, iy0, iz0, fx * gy0 * gz0)
    CORNER(ix1, iy0, iz1, fx * gy0 * fz)
    CORNER(ix1, iy1, iz0, fx * fy * gz0)
    CORNER(ix1, iy1, iz1, fx * fy * fz)
#undef CORNER

    size_t ob = ((size_t)b * CH + cg * 8) * NPTS + n;
#pragma unroll
    for (int j = 0; j < 8; j++) out[ob + (size_t)j * NPTS] = acc8[j];
}

// ---------------- launch ----------------------------------------------------
extern "C" void kernel_launch(void* const* d_in, const int* in_sizes, int n_in,
                              void* d_out, int out_size) {
    (void)in_sizes; (void)n_in; (void)out_size;
    const float* feats  = (const float*)d_in[0];
    const float* coords = (const float*)d_in[1];
    const float* w1  = (const float*)d_in[2];
    const float* b1  = (const float*)d_in[3];
    const float* g1  = (const float*)d_in[4];
    const float* be1 = (const float*)d_in[5];
    const float* m1  = (const float*)d_in[6];
    const float* v1  = (const float*)d_in[7];
    const float* w2  = (const float*)d_in[8];
    const float* b2  = (const float*)d_in[9];
    const float* g2  = (const float*)d_in[10];
    const float* be2 = (const float*)d_in[11];
    const float* m2  = (const float*)d_in[12];
    const float* v2  = (const float*)d_in[13];
    float* out = (float*)d_out;

    float *p_g0, *p_be1, *p_be2, *p_cnt;
    __half *p_gh1, *p_gh2;
    uint4 *p_wF1, *p_wF2;
    cudaGetSymbolAddress((void**)&p_g0, d_grid0);
    cudaGetSymbolAddress((void**)&p_gh1, d_gh1);
    cudaGetSymbolAddress((void**)&p_gh2, d_gh2);
    cudaGetSymbolAddress((void**)&p_wF1, d_wF1);
    cudaGetSymbolAddress((void**)&p_wF2, d_wF2);
    cudaGetSymbolAddress((void**)&p_be1, d_biasE1);
    cudaGetSymbolAddress((void**)&p_be2, d_biasE2);
    cudaGetSymbolAddress((void**)&p_cnt, d_cnt);

    cudaFuncSetAttribute(conv_tc_kernel<false>,
                         cudaFuncAttributeMaxDynamicSharedMemorySize, C_SMEM);
    cudaFuncSetAttribute(conv_tc_kernel<true>,
                         cudaFuncAttributeMaxDynamicSharedMemorySize, C_SMEM);

    fused_init_kernel<<<ZBLK + 2 * WBLK + MBLK, 256>>>(coords,                       // 1
        w1, b1, g1, be1, m1, v1, w2, b2, g2, be2, m2, v2);
    scale_kernel<<<MBLK, 256>>>(coords);                                             // 2
    trans_scatter_kernel<<<dim3(NPTS / 32, 2, BATCH), dim3(32, 8)>>>(feats, coords); // 3
    conv_tc_kernel<false><<<BATCH * 128, 256, C_SMEM>>>(p_g0, p_gh1, p_wF1,          // 4 (ncu)
                                                        p_be1, p_cnt);
    conv_tc_kernel<true><<<BATCH * 128, 256, C_SMEM>>>(p_gh1, p_gh2, p_wF2,          // 5
                                                       p_be2, nullptr);
    devox_kernel<<<dim3(NPTS / 256, 9, BATCH), 256>>>(out, p_gh2, coords);           // 6
}